// round 1
// baseline (speedup 1.0000x reference)
#include <cuda_runtime.h>
#include <math.h>

// Problem constants (from reference)
#define BS        1048576
#define N_AGENTS  8
#define N_HEAD    4
#define EMBED_DIM 64

// Output layout (flattened tuple, float32):
//   [0, BS*N_AGENTS)                       head_attend  = 0.5 everywhere
//   [BS*N_AGENTS, BS*N_AGENTS+BS)          v            = V[0] everywhere
//   [.. +1)                                attend_mag_regs (scalar)
//   [.. +4)                                head_entropies = -log(0.125+1e-8)
#define HA_ELEMS   (BS * N_AGENTS)          // 8388608
#define V_ELEMS    (BS)                     // 1048576
#define HA_VEC4    (HA_ELEMS / 4)           // 2097152
#define V_VEC4     (V_ELEMS / 4)            // 262144
#define FILL_VEC4  (HA_VEC4 + V_VEC4)       // 2359296

#define THREADS    256
#define FILL_BLOCKS ((FILL_VEC4 + THREADS - 1) / THREADS)  // 9216

__global__ __launch_bounds__(THREADS)
void qatten_fused_kernel(const float* __restrict__ sel_w,
                         const float* __restrict__ key_w,
                         const float* __restrict__ V,
                         float* __restrict__ out) {
    const int bid = blockIdx.x;

    if (bid < FILL_BLOCKS) {
        // ---- Fill path: pure STG.128, store-roofline bound ----
        const long long idx = (long long)bid * THREADS + threadIdx.x;
        if (idx < FILL_VEC4) {
            float4* out4 = reinterpret_cast<float4*>(out);
            if (idx < HA_VEC4) {
                out4[idx] = make_float4(0.5f, 0.5f, 0.5f, 0.5f);
            } else {
                const float v = V[0];           // L2/const hit, negligible
                out4[idx] = make_float4(v, v, v, v);
            }
        }
        return;
    }

    // ---- Tail block: scalar reg term + entropies ----
    // 256 threads: thread t handles head h = t/64, element k = t%64.
    __shared__ float warp_sums[THREADS / 32];  // 8 warps, 2 per head

    const int t   = threadIdx.x;
    const int wid = t >> 5;
    float p = sel_w[t] * key_w[t];   // sel_w/key_w are (4,64) contiguous = 256 elems

    // warp reduce
    #pragma unroll
    for (int off = 16; off > 0; off >>= 1)
        p += __shfl_down_sync(0xFFFFFFFFu, p, off);
    if ((t & 31) == 0) warp_sums[wid] = p;
    __syncthreads();

    if (t == 0) {
        float reg = 0.0f;
        #pragma unroll
        for (int h = 0; h < N_HEAD; h++) {
            float dot_h = warp_sums[2 * h] + warp_sums[2 * h + 1];
            reg += dot_h * dot_h;
        }
        out[HA_ELEMS + V_ELEMS] = 0.001f * reg;

        // softmax of constant logits over 8 agents -> p = 1/8 exactly
        const float prob = 0.125f;
        const float ent  = -(8.0f * prob * logf(prob + 1e-8f));
        #pragma unroll
        for (int h = 0; h < N_HEAD; h++)
            out[HA_ELEMS + V_ELEMS + 1 + h] = ent;
    }
}

extern "C" void kernel_launch(void* const* d_in, const int* in_sizes, int n_in,
                              void* d_out, int out_size) {
    // metadata order: agent_qs(f32), actions(i64), sel_w(f32), key_w(f32), V(f32)
    const float* sel_w = (const float*)d_in[2];
    const float* key_w = (const float*)d_in[3];
    const float* V     = (const float*)d_in[4];
    float* out = (float*)d_out;

    qatten_fused_kernel<<<FILL_BLOCKS + 1, THREADS>>>(sel_w, key_w, V, out);
}